// round 10
// baseline (speedup 1.0000x reference)
#include <cuda_runtime.h>
#include <cuda_fp16.h>
#include <math.h>

#define NMAX 100000
#define EMAX 3200000
#define D 128
#define KSTEPS 10
#define LVLS (KSTEPS + 1)

// ---- scratch (allocation-free rule: static __device__ arrays) ----
// All 11 propagation levels, pre-scaled by src_norm, fp16: G[k] = h_k * srcn
__device__ __half2 g_G[(size_t)LVLS * NMAX * (D / 2)];   // 282 MB
__device__ int     g_indeg[NMAX];
__device__ int     g_outdeg[NMAX];
__device__ float   g_w[NMAX];        // dstn * srcn (spmm output scale)
__device__ float   g_srcn_inv[NMAX];
__device__ int     g_rowoff[NMAX + 1];
__device__ int     g_cursor[NMAX];   // seeded by k_scan to rowoff start
__device__ int     g_csr[EMAX];

__global__ void k_zero(int n) {
    int i = blockIdx.x * blockDim.x + threadIdx.x;
    if (i < n) { g_indeg[i] = 0; g_outdeg[i] = 0; }
}

__global__ void k_count(const int* __restrict__ src, const int* __restrict__ dst, int e) {
    int i = blockIdx.x * blockDim.x + threadIdx.x;
    if (i < e) {
        atomicAdd(&g_indeg[dst[i]], 1);
        atomicAdd(&g_outdeg[src[i]], 1);
    }
}

// warp per node: computes norms (same math/order as before) and
// G[0] = feats * src_norm (fp16). Replaces separate k_norm.
__global__ void k_copy(const float* __restrict__ feats, int n) {
    int gw   = (blockIdx.x * blockDim.x + threadIdx.x) >> 5;
    int lane = threadIdx.x & 31;
    if (gw >= n) return;

    float dn = rsqrtf((float)max(g_indeg[gw], 1));
    float sd = sqrtf((float)max(g_outdeg[gw], 1));
    float sn = 1.f / sd;
    if (lane == 0) {
        g_srcn_inv[gw] = sd;
        g_w[gw]        = dn * sn;
    }

    float4 v = reinterpret_cast<const float4*>(feats)[(size_t)gw * (D / 4) + lane];
    __half2 p0 = __floats2half2_rn(v.x * sn, v.y * sn);
    __half2 p1 = __floats2half2_rn(v.z * sn, v.w * sn);
    uint2 ow;
    ow.x = *reinterpret_cast<unsigned int*>(&p0);
    ow.y = *reinterpret_cast<unsigned int*>(&p1);
    *reinterpret_cast<uint2*>(g_G + (size_t)gw * (D / 2) + 2 * lane) = ow;
}

// single-block exclusive scan of indeg -> rowoff, parallel (warp-shuffle
// two-level scan, no serial thread-0 pass). Also seeds cursor = rowoff.
__global__ void k_scan(int n) {
    __shared__ int wsum[32];
    int t = threadIdx.x;
    int lane = t & 31, wid = t >> 5;
    int chunk = (n + 1023) / 1024;
    int start = t * chunk;
    int end   = min(start + chunk, n);
    int s = 0;
    for (int i = start; i < end; i++) s += g_indeg[i];

    // inclusive warp scan of per-thread sums
    int v = s;
    #pragma unroll
    for (int o = 1; o < 32; o <<= 1) {
        int x = __shfl_up_sync(0xFFFFFFFFu, v, o);
        if (lane >= o) v += x;
    }
    if (lane == 31) wsum[wid] = v;
    __syncthreads();
    if (wid == 0) {
        int w = wsum[lane];
        #pragma unroll
        for (int o = 1; o < 32; o <<= 1) {
            int x = __shfl_up_sync(0xFFFFFFFFu, w, o);
            if (lane >= o) w += x;
        }
        wsum[lane] = w;   // inclusive warp totals
    }
    __syncthreads();

    int excl = v - s + (wid ? wsum[wid - 1] : 0);   // exclusive prefix for this thread
    if (t == 1023) g_rowoff[n] = wsum[31];
    int acc = excl;
    for (int i = start; i < end; i++) {
        g_rowoff[i] = acc;
        g_cursor[i] = acc;           // seed fill cursor with row start
        acc += g_indeg[i];
    }
}

__global__ void k_fill(const int* __restrict__ src, const int* __restrict__ dst, int e) {
    int i = blockIdx.x * blockDim.x + threadIdx.x;
    if (i < e) {
        int p = atomicAdd(&g_cursor[dst[i]], 1);
        g_csr[p] = src[i];
    }
}

__device__ __forceinline__ void acc8(uint4 raw, float* a) {
    __half2 h0 = *reinterpret_cast<__half2*>(&raw.x);
    __half2 h1 = *reinterpret_cast<__half2*>(&raw.y);
    __half2 h2 = *reinterpret_cast<__half2*>(&raw.z);
    __half2 h3 = *reinterpret_cast<__half2*>(&raw.w);
    float2 f0 = __half22float2(h0);
    float2 f1 = __half22float2(h1);
    float2 f2 = __half22float2(h2);
    float2 f3 = __half22float2(h3);
    a[0] += f0.x; a[1] += f0.y; a[2] += f1.x; a[3] += f1.y;
    a[4] += f2.x; a[5] += f2.y; a[6] += f3.x; a[7] += f3.y;
}

// pull-based SpMM (round-7 proven version): one warp per dst node, TWO edges
// per warp-iteration. Half-warp covers the full 256B row of its edge via
// uint4. csr chunk loaded coalesced, broadcast via shfl. Remainder is a
// rolled pair loop with WARP-UNIFORM bound (no divergence).
__global__ void k_spmm(int n, int k) {
    int gw   = (blockIdx.x * blockDim.x + threadIdx.x) >> 5;
    int lane = threadIdx.x & 31;
    if (gw >= n) return;
    int beg = g_rowoff[gw];
    int end = g_rowoff[gw + 1];
    const uint4* __restrict__ Gin =
        reinterpret_cast<const uint4*>(g_G + (size_t)(k - 1) * NMAX * (D / 2));
    int h    = lane & 15;   // 16B slot within the 256B row
    int half = lane >> 4;   // which edge of the pair this lane serves

    float a[8];
    #pragma unroll
    for (int d = 0; d < 8; d++) a[d] = 0.f;

    int i = beg;
    for (; i + 32 <= end; i += 32) {
        int idx = g_csr[i + lane];                 // coalesced, 1 load / 32 edges
        #pragma unroll
        for (int j = 0; j < 16; j++) {
            int u = __shfl_sync(0xFFFFFFFFu, idx, 2 * j + half);
            acc8(Gin[(size_t)u * 16 + h], a);
        }
    }
    int m = end - i;
    if (m > 0) {
        int idx = (lane < m) ? g_csr[i + lane] : 0;
        int j = 0;
        for (; j + 2 <= m; j += 2) {               // warp-uniform bound
            int u = __shfl_sync(0xFFFFFFFFu, idx, j + half);
            acc8(Gin[(size_t)u * 16 + h], a);
        }
        if (j < m) {
            int u = __shfl_sync(0xFFFFFFFFu, idx, j);
            if (half == 0) acc8(Gin[(size_t)u * 16 + h], a);
        }
    }

    // fold edge-A / edge-B partials
    #pragma unroll
    for (int d = 0; d < 8; d++) a[d] += __shfl_xor_sync(0xFFFFFFFFu, a[d], 16);

    // G[k] = (acc * dstn) * srcn, stored fp16 pre-scaled for next gather
    float w = g_w[gw];
    if (lane < 16) {
        __half2 o0 = __floats2half2_rn(a[0] * w, a[1] * w);
        __half2 o1 = __floats2half2_rn(a[2] * w, a[3] * w);
        __half2 o2 = __floats2half2_rn(a[4] * w, a[5] * w);
        __half2 o3 = __floats2half2_rn(a[6] * w, a[7] * w);
        uint4 ow;
        ow.x = *reinterpret_cast<unsigned int*>(&o0);
        ow.y = *reinterpret_cast<unsigned int*>(&o1);
        ow.z = *reinterpret_cast<unsigned int*>(&o2);
        ow.w = *reinterpret_cast<unsigned int*>(&o3);
        reinterpret_cast<uint4*>(g_G + ((size_t)k * NMAX + gw) * (D / 2))[h] = ow;
    }
}

// gated combination from the 11 fp16 level buffers: one warp per node.
__global__ void k_final(const float* __restrict__ s, float* __restrict__ out, int n) {
    int gw   = (blockIdx.x * blockDim.x + threadIdx.x) >> 5;
    int lane = threadIdx.x & 31;
    if (gw >= n) return;

    float4 sv = reinterpret_cast<const float4*>(s)[lane];
    float inv = g_srcn_inv[gw];
    size_t base = (size_t)gw * (D / 2) + 2 * lane;

    float ax = 0.f, ay = 0.f, az = 0.f, aw = 0.f;
    #pragma unroll
    for (int k = 0; k < LVLS; k++) {
        uint2 raw = *reinterpret_cast<const uint2*>(g_G + (size_t)k * NMAX * (D / 2) + base);
        __half2 p0 = *reinterpret_cast<__half2*>(&raw.x);
        __half2 p1 = *reinterpret_cast<__half2*>(&raw.y);
        float2 f0 = __half22float2(p0);
        float2 f1 = __half22float2(p1);

        float pd = f0.x * sv.x + f0.y * sv.y + f1.x * sv.z + f1.y * sv.w;
        #pragma unroll
        for (int o = 16; o; o >>= 1) pd += __shfl_xor_sync(0xFFFFFFFFu, pd, o);
        float sg = 1.f / (1.f + expf(-pd * inv));

        ax = fmaf(sg, f0.x, ax);
        ay = fmaf(sg, f0.y, ay);
        az = fmaf(sg, f1.x, az);
        aw = fmaf(sg, f1.y, aw);
    }
    float4 o = make_float4(ax * inv, ay * inv, az * inv, aw * inv);
    reinterpret_cast<float4*>(out)[(size_t)gw * (D / 4) + lane] = o;
}

extern "C" void kernel_launch(void* const* d_in, const int* in_sizes, int n_in,
                              void* d_out, int out_size) {
    const float* feats = (const float*)d_in[0];
    const float* s     = (const float*)d_in[1];
    const int*   src   = (const int*)d_in[2];
    const int*   dst   = (const int*)d_in[3];
    float* out = (float*)d_out;
    int n = in_sizes[0] / D;   // 100000
    int e = in_sizes[2];       // 3200000
    const int T = 256;

    k_zero <<<(n + T - 1) / T, T>>>(n);
    k_count<<<(e + T - 1) / T, T>>>(src, dst, e);

    int warps_grid = (n * 32 + T - 1) / T;
    k_copy <<<warps_grid, T>>>(feats, n);
    k_scan <<<1, 1024>>>(n);
    k_fill <<<(e + T - 1) / T, T>>>(src, dst, e);

    for (int k = 1; k <= KSTEPS; k++)
        k_spmm<<<warps_grid, T>>>(n, k);

    k_final<<<warps_grid, T>>>(s, out, n);
}

// round 11
// speedup vs baseline: 1.1671x; 1.1671x over previous
#include <cuda_runtime.h>
#include <cuda_fp16.h>
#include <math.h>

#define NMAX 100000
#define EMAX 3200000
#define D 128
#define KSTEPS 10
#define LVLS (KSTEPS + 1)
#define SCAN_B 1024
#define SCAN_NB ((NMAX + SCAN_B - 1) / SCAN_B)   // 98

// ---- scratch (allocation-free rule: static __device__ arrays) ----
// All 11 propagation levels, pre-scaled by src_norm, fp16: G[k] = h_k * srcn
__device__ __half2 g_G[(size_t)LVLS * NMAX * (D / 2)];   // 282 MB
__device__ int     g_indeg[NMAX];
__device__ int     g_outdeg[NMAX];
__device__ float   g_w[NMAX];        // dstn * srcn (spmm output scale)
__device__ float   g_srcn[NMAX];
__device__ float   g_srcn_inv[NMAX];
__device__ int     g_rowoff[NMAX + 1];
__device__ int     g_cursor[NMAX];   // seeded to rowoff by scan3
__device__ int     g_csr[EMAX];
__device__ int     g_bsum[SCAN_NB];
__device__ int     g_boff[SCAN_NB];

__global__ void k_zero(int n) {
    int i = blockIdx.x * blockDim.x + threadIdx.x;
    if (i < n) { g_indeg[i] = 0; g_outdeg[i] = 0; }
}

__global__ void k_count(const int* __restrict__ src, const int* __restrict__ dst, int e) {
    int i = blockIdx.x * blockDim.x + threadIdx.x;
    if (i < e) {
        atomicAdd(&g_indeg[dst[i]], 1);
        atomicAdd(&g_outdeg[src[i]], 1);
    }
}

__global__ void k_norm(int n) {
    int i = blockIdx.x * blockDim.x + threadIdx.x;
    if (i < n) {
        float dn = rsqrtf((float)max(g_indeg[i], 1));
        float sd = sqrtf((float)max(g_outdeg[i], 1));
        float sn = 1.f / sd;
        g_srcn[i]     = sn;
        g_srcn_inv[i] = sd;
        g_w[i]        = dn * sn;
    }
}

// warp per node: G[0] = feats * src_norm (fp16)
__global__ void k_copy(const float* __restrict__ feats, int n) {
    int gw   = (blockIdx.x * blockDim.x + threadIdx.x) >> 5;
    int lane = threadIdx.x & 31;
    if (gw >= n) return;

    float4 v = reinterpret_cast<const float4*>(feats)[(size_t)gw * (D / 4) + lane];
    float sn = g_srcn[gw];
    __half2 p0 = __floats2half2_rn(v.x * sn, v.y * sn);
    __half2 p1 = __floats2half2_rn(v.z * sn, v.w * sn);
    uint2 ow;
    ow.x = *reinterpret_cast<unsigned int*>(&p0);
    ow.y = *reinterpret_cast<unsigned int*>(&p1);
    *reinterpret_cast<uint2*>(g_G + (size_t)gw * (D / 2) + 2 * lane) = ow;
}

// ---- multi-block coalesced scan (replaces the 168us single-block scan) ----
// scan1: block-local exclusive scan of indeg (coalesced), per-block sums
__global__ void k_scan1(int n) {
    __shared__ int wsum[32];
    int t = threadIdx.x, b = blockIdx.x;
    int i = b * SCAN_B + t;
    int lane = t & 31, wid = t >> 5;
    int x = (i < n) ? g_indeg[i] : 0;

    int v = x;
    #pragma unroll
    for (int o = 1; o < 32; o <<= 1) {
        int y = __shfl_up_sync(0xFFFFFFFFu, v, o);
        if (lane >= o) v += y;
    }
    if (lane == 31) wsum[wid] = v;
    __syncthreads();
    if (wid == 0) {
        int w = wsum[lane];
        #pragma unroll
        for (int o = 1; o < 32; o <<= 1) {
            int y = __shfl_up_sync(0xFFFFFFFFu, w, o);
            if (lane >= o) w += y;
        }
        wsum[lane] = w;
    }
    __syncthreads();

    int incl = v + (wid ? wsum[wid - 1] : 0);
    if (i < n) g_rowoff[i] = incl - x;             // block-local exclusive
    if (t == SCAN_B - 1) g_bsum[b] = incl;
}

// scan2: one block scans the 98 block sums (exclusive), writes total
__global__ void k_scan2(int n) {
    __shared__ int sh[SCAN_NB];
    int t = threadIdx.x;
    if (t < SCAN_NB) sh[t] = g_bsum[t];
    __syncthreads();
    if (t == 0) {
        int acc = 0;
        for (int b = 0; b < SCAN_NB; b++) { int v = sh[b]; g_boff[b] = acc; acc += v; }
        g_rowoff[n] = acc;
    }
}

// scan3: add block offsets, seed cursor = rowoff (coalesced)
__global__ void k_scan3(int n) {
    int t = threadIdx.x, b = blockIdx.x;
    int i = b * SCAN_B + t;
    if (i < n) {
        int r = g_rowoff[i] + g_boff[b];
        g_rowoff[i] = r;
        g_cursor[i] = r;
    }
}

__global__ void k_fill(const int* __restrict__ src, const int* __restrict__ dst, int e) {
    int i = blockIdx.x * blockDim.x + threadIdx.x;
    if (i < e) {
        int p = atomicAdd(&g_cursor[dst[i]], 1);
        g_csr[p] = src[i];
    }
}

__device__ __forceinline__ void acc8(uint4 raw, float* a) {
    __half2 h0 = *reinterpret_cast<__half2*>(&raw.x);
    __half2 h1 = *reinterpret_cast<__half2*>(&raw.y);
    __half2 h2 = *reinterpret_cast<__half2*>(&raw.z);
    __half2 h3 = *reinterpret_cast<__half2*>(&raw.w);
    float2 f0 = __half22float2(h0);
    float2 f1 = __half22float2(h1);
    float2 f2 = __half22float2(h2);
    float2 f3 = __half22float2(h3);
    a[0] += f0.x; a[1] += f0.y; a[2] += f1.x; a[3] += f1.y;
    a[4] += f2.x; a[5] += f2.y; a[6] += f3.x; a[7] += f3.y;
}

// pull-based SpMM (round-7 proven version, untouched): one warp per dst node,
// TWO edges per warp-iteration, uint4 per half-warp, shfl-broadcast indices,
// rolled remainder with warp-uniform bound.
__global__ void k_spmm(int n, int k) {
    int gw   = (blockIdx.x * blockDim.x + threadIdx.x) >> 5;
    int lane = threadIdx.x & 31;
    if (gw >= n) return;
    int beg = g_rowoff[gw];
    int end = g_rowoff[gw + 1];
    const uint4* __restrict__ Gin =
        reinterpret_cast<const uint4*>(g_G + (size_t)(k - 1) * NMAX * (D / 2));
    int h    = lane & 15;
    int half = lane >> 4;

    float a[8];
    #pragma unroll
    for (int d = 0; d < 8; d++) a[d] = 0.f;

    int i = beg;
    for (; i + 32 <= end; i += 32) {
        int idx = g_csr[i + lane];
        #pragma unroll
        for (int j = 0; j < 16; j++) {
            int u = __shfl_sync(0xFFFFFFFFu, idx, 2 * j + half);
            acc8(Gin[(size_t)u * 16 + h], a);
        }
    }
    int m = end - i;
    if (m > 0) {
        int idx = (lane < m) ? g_csr[i + lane] : 0;
        int j = 0;
        for (; j + 2 <= m; j += 2) {
            int u = __shfl_sync(0xFFFFFFFFu, idx, j + half);
            acc8(Gin[(size_t)u * 16 + h], a);
        }
        if (j < m) {
            int u = __shfl_sync(0xFFFFFFFFu, idx, j);
            if (half == 0) acc8(Gin[(size_t)u * 16 + h], a);
        }
    }

    #pragma unroll
    for (int d = 0; d < 8; d++) a[d] += __shfl_xor_sync(0xFFFFFFFFu, a[d], 16);

    float w = g_w[gw];
    if (lane < 16) {
        __half2 o0 = __floats2half2_rn(a[0] * w, a[1] * w);
        __half2 o1 = __floats2half2_rn(a[2] * w, a[3] * w);
        __half2 o2 = __floats2half2_rn(a[4] * w, a[5] * w);
        __half2 o3 = __floats2half2_rn(a[6] * w, a[7] * w);
        uint4 ow;
        ow.x = *reinterpret_cast<unsigned int*>(&o0);
        ow.y = *reinterpret_cast<unsigned int*>(&o1);
        ow.z = *reinterpret_cast<unsigned int*>(&o2);
        ow.w = *reinterpret_cast<unsigned int*>(&o3);
        reinterpret_cast<uint4*>(g_G + ((size_t)k * NMAX + gw) * (D / 2))[h] = ow;
    }
}

// gated combination from the 11 fp16 level buffers: one warp per node.
__global__ void k_final(const float* __restrict__ s, float* __restrict__ out, int n) {
    int gw   = (blockIdx.x * blockDim.x + threadIdx.x) >> 5;
    int lane = threadIdx.x & 31;
    if (gw >= n) return;

    float4 sv = reinterpret_cast<const float4*>(s)[lane];
    float inv = g_srcn_inv[gw];
    size_t base = (size_t)gw * (D / 2) + 2 * lane;

    float ax = 0.f, ay = 0.f, az = 0.f, aw = 0.f;
    #pragma unroll
    for (int k = 0; k < LVLS; k++) {
        uint2 raw = *reinterpret_cast<const uint2*>(g_G + (size_t)k * NMAX * (D / 2) + base);
        __half2 p0 = *reinterpret_cast<__half2*>(&raw.x);
        __half2 p1 = *reinterpret_cast<__half2*>(&raw.y);
        float2 f0 = __half22float2(p0);
        float2 f1 = __half22float2(p1);

        float pd = f0.x * sv.x + f0.y * sv.y + f1.x * sv.z + f1.y * sv.w;
        #pragma unroll
        for (int o = 16; o; o >>= 1) pd += __shfl_xor_sync(0xFFFFFFFFu, pd, o);
        float sg = 1.f / (1.f + expf(-pd * inv));

        ax = fmaf(sg, f0.x, ax);
        ay = fmaf(sg, f0.y, ay);
        az = fmaf(sg, f1.x, az);
        aw = fmaf(sg, f1.y, aw);
    }
    float4 o = make_float4(ax * inv, ay * inv, az * inv, aw * inv);
    reinterpret_cast<float4*>(out)[(size_t)gw * (D / 4) + lane] = o;
}

extern "C" void kernel_launch(void* const* d_in, const int* in_sizes, int n_in,
                              void* d_out, int out_size) {
    const float* feats = (const float*)d_in[0];
    const float* s     = (const float*)d_in[1];
    const int*   src   = (const int*)d_in[2];
    const int*   dst   = (const int*)d_in[3];
    float* out = (float*)d_out;
    int n = in_sizes[0] / D;   // 100000
    int e = in_sizes[2];       // 3200000
    const int T = 256;

    k_zero <<<(n + T - 1) / T, T>>>(n);
    k_count<<<(e + T - 1) / T, T>>>(src, dst, e);
    k_norm <<<(n + T - 1) / T, T>>>(n);

    int warps_grid = (n * 32 + T - 1) / T;
    k_copy <<<warps_grid, T>>>(feats, n);

    k_scan1<<<SCAN_NB, SCAN_B>>>(n);
    k_scan2<<<1, 128>>>(n);
    k_scan3<<<SCAN_NB, SCAN_B>>>(n);

    k_fill <<<(e + T - 1) / T, T>>>(src, dst, e);

    for (int k = 1; k <= KSTEPS; k++)
        k_spmm<<<warps_grid, T>>>(n, k);

    k_final<<<warps_grid, T>>>(s, out, n);
}